// round 4
// baseline (speedup 1.0000x reference)
#include <cuda_runtime.h>
#include <cuda_fp16.h>
#include <cstdint>

// ---------------- problem constants ----------------
constexpr int B  = 16384;
constexpr int F  = 24;
constexpr int P  = 276;
constexpr int MT = 128;                  // b-rows per CTA
constexpr int NTILE = B / MT;            // 128 b-tiles
constexpr int XTILE = MT * 128;          // 16 KB per (tile, field), fp16, swizzled
constexpr int WTILE = 64 * 128;          // 8 KB per pair (W^T fp16, swizzled)
constexpr unsigned WOFF = 12 * XTILE;            // 196608
constexpr unsigned DYN_SMEM = WOFF + 4 * WTILE;  // 229376 (224 KB, ring of 4)

// ---------------- device scratch (allocation-guard safe) ----------------
__device__ __half g_xs[(size_t)NTILE * F * (XTILE / 2)];  // 48 MB preswizzled x tiles
__device__ __half g_ws[(size_t)P * (WTILE / 2)];          // 2.25 MB preswizzled W^T tiles

// ---------------- helpers ----------------
__device__ __forceinline__ unsigned smem_u32(const void* p) {
    return (unsigned)__cvta_generic_to_shared(p);
}
__device__ __forceinline__ void cp16(unsigned dst, const void* src) {
    asm volatile("cp.async.cg.shared.global [%0], [%1], 16;" :: "r"(dst), "l"(src));
}
__device__ __forceinline__ void cp_commit() {
    asm volatile("cp.async.commit_group;" ::: "memory");
}
__device__ __forceinline__ void cp_wait2() {
    asm volatile("cp.async.wait_group 2;" ::: "memory");
}
__device__ __forceinline__ void ldm_x4(unsigned addr, unsigned& r0, unsigned& r1,
                                       unsigned& r2, unsigned& r3) {
    asm volatile("ldmatrix.sync.aligned.m8n8.x4.shared.b16 {%0,%1,%2,%3}, [%4];"
                 : "=r"(r0), "=r"(r1), "=r"(r2), "=r"(r3)
                 : "r"(addr));
}
__device__ __forceinline__ void mma16816(float* c, const unsigned* a,
                                         unsigned b0, unsigned b1) {
    asm volatile(
        "mma.sync.aligned.m16n8k16.row.col.f32.f16.f16.f32 "
        "{%0,%1,%2,%3}, {%4,%5,%6,%7}, {%8,%9}, {%0,%1,%2,%3};"
        : "+f"(c[0]), "+f"(c[1]), "+f"(c[2]), "+f"(c[3])
        : "r"(a[0]), "r"(a[1]), "r"(a[2]), "r"(a[3]), "r"(b0), "r"(b1));
}
__device__ __forceinline__ int pidx(int fi, int fj) {   // triu row-major pair index
    return fi * (2 * F - fi - 1) / 2 + (fj - fi - 1);
}

// ---------------- prepass: convert + pre-swizzle ----------------
__global__ void convert_x_kernel(const float* __restrict__ x) {
    int t = blockIdx.x * blockDim.x + threadIdx.x;      // chunk id < B*F*8
    int c = t & 7;
    int bf = t >> 3;
    int f = bf % F;
    int b = bf / F;
    const float4* src = reinterpret_cast<const float4*>(x + ((size_t)bf * 64 + c * 8));
    float4 v0 = src[0], v1 = src[1];
    union { uint4 u; __half2 h[4]; } pk;
    pk.h[0] = __floats2half2_rn(v0.x, v0.y);
    pk.h[1] = __floats2half2_rn(v0.z, v0.w);
    pk.h[2] = __floats2half2_rn(v1.x, v1.y);
    pk.h[3] = __floats2half2_rn(v1.z, v1.w);
    int tile = b >> 7, r = b & 127;
    size_t off = ((size_t)(tile * 24 + f) << 14) + r * 128 + ((c ^ (r & 7)) << 4);
    *reinterpret_cast<uint4*>(reinterpret_cast<char*>(g_xs) + off) = pk.u;
}
// W[p,d,e] fp32 -> preswizzled W^T tile: row e, chunk c holds d = c*8..c*8+7
__global__ void convert_w_kernel(const float* __restrict__ W) {
    int t = blockIdx.x * blockDim.x + threadIdx.x;      // < P*8*64
    int e = t & 63;
    int pc = t >> 6;
    int c = pc & 7;
    int p = pc >> 3;
    const float* base = W + (size_t)p * 4096 + (size_t)c * 8 * 64 + e;
    union { uint4 u; __half h[8]; } pk;
    #pragma unroll
    for (int k = 0; k < 8; k++) pk.h[k] = __float2half_rn(base[k * 64]);
    size_t off = (size_t)p * 8192 + e * 128 + ((c ^ (e & 7)) << 4);
    *reinterpret_cast<uint4*>(reinterpret_cast<char*>(g_ws) + off) = pk.u;
}
__global__ void zero_out_kernel(float* __restrict__ out) {
    out[blockIdx.x * blockDim.x + threadIdx.x] = 0.0f;
}

// ---------------- main kernel ----------------
// grid = (128 b-tiles, 6 types), 256 threads (8 warps).
// warp = wi + 4*wg: wi owns rows wi*32..+31, wg owns n-col half wg*32..+31.
// Per j: accumulate GEMM over i-partners in registers, one epilogue dot per j.
// W streamed through a 4-slot ring, prefetch distance 2, ONE barrier per pair.
__global__ __launch_bounds__(256, 1) void fmfm4_kernel(float* __restrict__ out) {
    extern __shared__ __align__(1024) char smem[];
    const int tid  = threadIdx.x;
    const int warp = tid >> 5, lane = tid & 31;
    const int wi = warp & 3, wg = warp >> 2;
    const int group = lane >> 2, tid4 = lane & 3;
    const int tile = blockIdx.x;
    const int type = blockIdx.y;
    const int b0   = tile * MT;

    const bool cross = (type >= 2);
    int fb0, fb1, nJ, npairs;
    if (!cross) { fb0 = type * 12; fb1 = 0; nJ = 11; npairs = 66; }
    else {
        int t = type - 2;
        fb0 = (t >> 1) * 6;          // i-side fields -> slots 0..5
        fb1 = 12 + (t & 1) * 6;      // j-side fields -> slots 6..11
        nJ = 6; npairs = 36;
    }

    const unsigned sb = smem_u32(smem);

    // ---- group 0: 12 x field tiles (preswizzled, linear copy) ----
    #pragma unroll
    for (int s = 0; s < 12; s++) {
        int f = cross ? (s < 6 ? fb0 + s : fb1 + (s - 6)) : (fb0 + s);
        const char* g = reinterpret_cast<const char*>(g_xs) + ((size_t)(tile * 24 + f) << 14);
        #pragma unroll
        for (int c = tid; c < 1024; c += 256)
            cp16(sb + s * XTILE + c * 16, g + c * 16);
    }
    cp_commit();
    // ---- groups 1,2: W for pairs 0,1 ----
    #pragma unroll
    for (int m = 0; m < 2; m++) {
        int pfj, pfi;
        if (cross) { pfj = fb1 + m / 6; pfi = fb0 + m % 6; }
        else       { pfj = fb0 + 1 + (m > 0); pfi = fb0 + (m > 0 ? 0 : 0); }
        // m=0 -> (fb0, fb0+1); m=1 -> (fb0, fb0+2)  [within j-major order]
        if (!cross) { pfi = fb0; pfj = fb0 + 1 + m; }
        int p = pidx(pfi, pfj);
        const char* g = reinterpret_cast<const char*>(g_ws) + (size_t)p * WTILE;
        for (int c = tid; c < 512; c += 256)
            cp16(sb + WOFF + (unsigned)m * WTILE + c * 16, g + c * 16);
        cp_commit();
    }

    float tot[2][2] = {{0.f, 0.f}, {0.f, 0.f}};
    int n = 0;   // pair sequence counter (j-major)

    for (int jidx = 0; jidx < nJ; jidx++) {
        const int na = cross ? 6 : jidx + 1;     // number of i-partners
        const int jslot = cross ? 6 + jidx : jidx + 1;

        float acc[2][4][4];
        #pragma unroll
        for (int a = 0; a < 2; a++)
            #pragma unroll
            for (int b = 0; b < 4; b++)
                #pragma unroll
                for (int c = 0; c < 4; c++) acc[a][b][c] = 0.0f;

        for (int aa = 0; aa < na; aa++, n++) {
            // ---- prefetch W for pair n+2 into ring slot (n+2)&3 ----
            {
                int m = n + 2;
                if (m < npairs) {
                    int j2, i2;
                    if (cross) { j2 = m / 6; i2 = m % 6; }
                    else {
                        j2 = 0; int rem = m;
                        while (rem > j2) { rem -= j2 + 1; j2++; }
                        i2 = rem;
                    }
                    int pfi = fb0 + i2;
                    int pfj = cross ? fb1 + j2 : fb0 + j2 + 1;
                    int p = pidx(pfi, pfj);
                    const char* g = reinterpret_cast<const char*>(g_ws) + (size_t)p * WTILE;
                    unsigned dstb = sb + WOFF + ((unsigned)(m & 3)) * WTILE;
                    #pragma unroll
                    for (int c = tid; c < 512; c += 256)
                        cp16(dstb + c * 16, g + c * 16);
                }
                cp_commit();            // empty group on tail keeps accounting uniform
            }
            cp_wait2();                 // own chunks of group n complete
            __syncthreads();            // publish W slot n&3 (and x tiles on n=0)

            const unsigned xi_base = sb + (unsigned)aa * XTILE;
            const unsigned w_base  = sb + WOFF + ((unsigned)(n & 3)) * WTILE;

            #pragma unroll
            for (int ks = 0; ks < 4; ks++) {
                unsigned a[2][4];
                #pragma unroll
                for (int mt = 0; mt < 2; mt++) {
                    int r  = wi * 32 + mt * 16 + (lane & 15);
                    int ch = ks * 2 + (lane >> 4);
                    ldm_x4(xi_base + r * 128 + ((ch ^ (r & 7)) << 4),
                           a[mt][0], a[mt][1], a[mt][2], a[mt][3]);
                }
                #pragma unroll
                for (int h = 0; h < 2; h++) {
                    unsigned br0, br1, br2, br3;
                    int nt2 = wg * 2 + h;
                    int r  = nt2 * 16 + (lane & 15);
                    int ch = ks * 2 + (lane >> 4);
                    ldm_x4(w_base + r * 128 + ((ch ^ (r & 7)) << 4), br0, br1, br2, br3);
                    #pragma unroll
                    for (int mt = 0; mt < 2; mt++) {
                        mma16816(acc[mt][h * 2],     a[mt], br0, br2);
                        mma16816(acc[mt][h * 2 + 1], a[mt], br1, br3);
                    }
                }
            }
        }

        // ---- epilogue for j: dot rows of acc with x_j (this warp's col half) ----
        #pragma unroll
        for (int mt = 0; mt < 2; mt++) {
            const int r0 = wi * 32 + mt * 16 + group;
            const int r1 = r0 + 8;
            float s0 = 0.0f, s1 = 0.0f;
            const char* xj = smem + jslot * XTILE;
            #pragma unroll
            for (int hn = 0; hn < 4; hn++) {
                const int ntg = wg * 4 + hn;     // global 8-col tile index
                const __half2 x0 = *reinterpret_cast<const __half2*>(
                    xj + r0 * 128 + ((ntg ^ (r0 & 7)) << 4) + tid4 * 4);
                const __half2 x1 = *reinterpret_cast<const __half2*>(
                    xj + r1 * 128 + ((ntg ^ (r1 & 7)) << 4) + tid4 * 4);
                float2 f0 = __half22float2(x0);
                float2 f1 = __half22float2(x1);
                s0 = fmaf(acc[mt][hn][0], f0.x, s0);
                s0 = fmaf(acc[mt][hn][1], f0.y, s0);
                s1 = fmaf(acc[mt][hn][2], f1.x, s1);
                s1 = fmaf(acc[mt][hn][3], f1.y, s1);
            }
            tot[mt][0] += s0;
            tot[mt][1] += s1;
        }
    }

    // ---- final reduction + writeback (two wgs add into the same row) ----
    #pragma unroll
    for (int mt = 0; mt < 2; mt++)
        #pragma unroll
        for (int h = 0; h < 2; h++) {
            float v = tot[mt][h];
            v += __shfl_xor_sync(0xffffffffu, v, 1);
            v += __shfl_xor_sync(0xffffffffu, v, 2);
            if (tid4 == 0)
                atomicAdd(out + b0 + wi * 32 + mt * 16 + group + h * 8, v);
        }
}

// ---------------- launch ----------------
extern "C" void kernel_launch(void* const* d_in, const int* in_sizes, int n_in,
                              void* d_out, int out_size) {
    const float* x = (const float*)d_in[0];
    const float* W = (const float*)d_in[1];
    float* out = (float*)d_out;

    static bool attr_done = false;
    if (!attr_done) {
        cudaFuncSetAttribute(fmfm4_kernel, cudaFuncAttributeMaxDynamicSharedMemorySize, DYN_SMEM);
        attr_done = true;
    }

    convert_x_kernel<<<(B * F * 8) / 256, 256>>>(x);
    convert_w_kernel<<<(P * 8 * 64) / 256, 256>>>(W);
    zero_out_kernel<<<B / 256, 256>>>(out);

    dim3 grid(NTILE, 6);
    fmfm4_kernel<<<grid, 256, DYN_SMEM>>>(out);
}

// round 6
// speedup vs baseline: 1.0307x; 1.0307x over previous
#include <cuda_runtime.h>
#include <cuda_fp16.h>
#include <cstdint>

// ---------------- problem constants ----------------
constexpr int B  = 16384;
constexpr int F  = 24;
constexpr int P  = 276;
constexpr int MT = 128;                  // b-rows per CTA
constexpr int NTILE = B / MT;            // 128 b-tiles
constexpr int XTILE = MT * 128;          // 16 KB per (tile, field), fp16, swizzled
constexpr int WTILE = 64 * 128;          // 8 KB per pair (W^T fp16, swizzled)
constexpr unsigned XJOFF = 6u * XTILE;           //  98304 (2 xj buffers follow)
constexpr unsigned WOFF  = XJOFF + 2u * XTILE;   // 131072
constexpr unsigned WBUF  = 6u * WTILE;           //  49152 (one W group buffer)
constexpr unsigned DYN_SMEM = WOFF + 2u * WBUF;  // 229376 (224 KB)

// ---------------- device scratch (allocation-guard safe) ----------------
__device__ __half g_xs[(size_t)NTILE * F * (XTILE / 2)];  // 48 MB preswizzled x tiles
__device__ __half g_ws[(size_t)P * (WTILE / 2)];          // 2.25 MB preswizzled W^T tiles

// ---------------- helpers ----------------
__device__ __forceinline__ unsigned smem_u32(const void* p) {
    return (unsigned)__cvta_generic_to_shared(p);
}
__device__ __forceinline__ void cp16(unsigned dst, const void* src) {
    asm volatile("cp.async.cg.shared.global [%0], [%1], 16;" :: "r"(dst), "l"(src));
}
__device__ __forceinline__ void cp_commit() {
    asm volatile("cp.async.commit_group;" ::: "memory");
}
__device__ __forceinline__ void cp_wait0() {
    asm volatile("cp.async.wait_group 0;" ::: "memory");
}
__device__ __forceinline__ void ldm_x4(unsigned addr, unsigned& r0, unsigned& r1,
                                       unsigned& r2, unsigned& r3) {
    asm volatile("ldmatrix.sync.aligned.m8n8.x4.shared.b16 {%0,%1,%2,%3}, [%4];"
                 : "=r"(r0), "=r"(r1), "=r"(r2), "=r"(r3)
                 : "r"(addr));
}
__device__ __forceinline__ void mma16816(float* c, const unsigned* a,
                                         unsigned b0, unsigned b1) {
    asm volatile(
        "mma.sync.aligned.m16n8k16.row.col.f32.f16.f16.f32 "
        "{%0,%1,%2,%3}, {%4,%5,%6,%7}, {%8,%9}, {%0,%1,%2,%3};"
        : "+f"(c[0]), "+f"(c[1]), "+f"(c[2]), "+f"(c[3])
        : "r"(a[0]), "r"(a[1]), "r"(a[2]), "r"(a[3]), "r"(b0), "r"(b1));
}
__device__ __forceinline__ int pidx(int fi, int fj) {   // triu row-major pair index
    return fi * (2 * F - fi - 1) / 2 + (fj - fi - 1);
}

// ---------------- prepass: convert + pre-swizzle ----------------
__global__ void convert_x_kernel(const float* __restrict__ x) {
    int t = blockIdx.x * blockDim.x + threadIdx.x;      // chunk id < B*F*8
    int c = t & 7;
    int bf = t >> 3;
    int f = bf % F;
    int b = bf / F;
    const float4* src = reinterpret_cast<const float4*>(x + ((size_t)bf * 64 + c * 8));
    float4 v0 = src[0], v1 = src[1];
    union { uint4 u; __half2 h[4]; } pk;
    pk.h[0] = __floats2half2_rn(v0.x, v0.y);
    pk.h[1] = __floats2half2_rn(v0.z, v0.w);
    pk.h[2] = __floats2half2_rn(v1.x, v1.y);
    pk.h[3] = __floats2half2_rn(v1.z, v1.w);
    int tile = b >> 7, r = b & 127;
    size_t off = ((size_t)(tile * 24 + f) << 14) + r * 128 + ((c ^ (r & 7)) << 4);
    *reinterpret_cast<uint4*>(reinterpret_cast<char*>(g_xs) + off) = pk.u;
}
// W[p,d,e] fp32 -> preswizzled W^T tile: row e, chunk c holds d = c*8..c*8+7
__global__ void convert_w_kernel(const float* __restrict__ W) {
    int t = blockIdx.x * blockDim.x + threadIdx.x;      // < P*8*64
    int e = t & 63;
    int pc = t >> 6;
    int c = pc & 7;
    int p = pc >> 3;
    const float* base = W + (size_t)p * 4096 + (size_t)c * 8 * 64 + e;
    union { uint4 u; __half h[8]; } pk;
    #pragma unroll
    for (int k = 0; k < 8; k++) pk.h[k] = __float2half_rn(base[k * 64]);
    size_t off = (size_t)p * 8192 + e * 128 + ((c ^ (e & 7)) << 4);
    *reinterpret_cast<uint4*>(reinterpret_cast<char*>(g_ws) + off) = pk.u;
}
__global__ void zero_out_kernel(float* __restrict__ out) {
    out[blockIdx.x * blockDim.x + threadIdx.x] = 0.0f;
}

// ---------------- main kernel ----------------
// 24 fields in 4 groups of 6. grid = (10 types, 128 b-tiles), 256 threads.
//   type 0..3  : within-group g        -> 15 pairs (j=1..5, i=0..j-1)
//   type 4..9  : cross block (gi,gj)   -> 36 pairs (j=0..5, i=0..5)
// 6 xi tiles resident; per j ONE cp.async group (W j-group + xj), ONE barrier,
// then the full K-concat MMA chain + epilogue dot. Double-buffered W/xj.
__global__ __launch_bounds__(256, 1) void fmfm5_kernel(float* __restrict__ out) {
    extern __shared__ __align__(1024) char smem[];
    const int tid  = threadIdx.x;
    const int warp = tid >> 5, lane = tid & 31;
    const int wi = warp & 3, wg = warp >> 2;
    const int group = lane >> 2, tid4 = lane & 3;
    const int type = blockIdx.x;
    const int tile = blockIdx.y;
    const int b0   = tile * MT;

    const bool cross = (type >= 4);
    int gi, gj;
    if (!cross) { gi = type; gj = type; }
    else {
        const int ta[6] = {0, 0, 0, 1, 1, 2};
        const int tb[6] = {1, 2, 3, 2, 3, 3};
        gi = ta[type - 4]; gj = tb[type - 4];
    }
    const int fi0 = gi * 6, fj0 = gj * 6;
    const int jstart = cross ? 0 : 1;

    const unsigned sb = smem_u32(smem);
    const char* xs = reinterpret_cast<const char*>(g_xs);
    const char* ws = reinterpret_cast<const char*>(g_ws);

    // ---- preload: 6 xi tiles + W group(jstart) + xj(jstart) ----
    #pragma unroll
    for (int s = 0; s < 6; s++) {
        const char* g = xs + ((size_t)(tile * 24 + fi0 + s) << 14);
        #pragma unroll
        for (int c = tid; c < 1024; c += 256)
            cp16(sb + s * XTILE + c * 16, g + c * 16);
    }
    {
        int nt0 = cross ? 6 : 1;
        unsigned wdst = sb + WOFF + (unsigned)(jstart & 1) * WBUF;
        for (int m = tid; m < nt0 * 512; m += 256) {
            int t = m >> 9, c = m & 511;
            const char* g = ws + (size_t)pidx(fi0 + t, fj0 + jstart) * WTILE;
            cp16(wdst + t * WTILE + c * 16, g + c * 16);
        }
        if (cross) {
            const char* g = xs + ((size_t)(tile * 24 + fj0 + jstart) << 14);
            for (int c = tid; c < 1024; c += 256)
                cp16(sb + XJOFF + (unsigned)(jstart & 1) * XTILE + c * 16, g + c * 16);
        }
    }
    cp_commit();

    float tot[2][2] = {{0.f, 0.f}, {0.f, 0.f}};

    for (int j = jstart; j <= 5; j++) {
        cp_wait0();
        __syncthreads();                 // publish group j (and retire reads of j-1 buffers)

        // ---- prefetch group j+1 (overlaps this j's MMA) ----
        {
            int jn = j + 1;
            if (jn <= 5) {
                int ntn = cross ? 6 : jn;
                unsigned wdst = sb + WOFF + (unsigned)(jn & 1) * WBUF;
                for (int m = tid; m < ntn * 512; m += 256) {
                    int t = m >> 9, c = m & 511;
                    const char* g = ws + (size_t)pidx(fi0 + t, fj0 + jn) * WTILE;
                    cp16(wdst + t * WTILE + c * 16, g + c * 16);
                }
                if (cross) {
                    const char* g = xs + ((size_t)(tile * 24 + fj0 + jn) << 14);
                    for (int c = tid; c < 1024; c += 256)
                        cp16(sb + XJOFF + (unsigned)(jn & 1) * XTILE + c * 16, g + c * 16);
                }
            }
            cp_commit();                 // empty group on last j keeps accounting uniform
        }

        // ---- MMA chain over i-partners (K-concat into acc) ----
        const int na = cross ? 6 : j;
        const unsigned wgrp = sb + WOFF + (unsigned)(j & 1) * WBUF;

        float acc[2][4][4];
        #pragma unroll
        for (int a = 0; a < 2; a++)
            #pragma unroll
            for (int b = 0; b < 4; b++)
                #pragma unroll
                for (int c = 0; c < 4; c++) acc[a][b][c] = 0.0f;

        for (int aa = 0; aa < na; aa++) {
            const unsigned xi_base = sb + (unsigned)aa * XTILE;
            const unsigned w_base  = wgrp + (unsigned)aa * WTILE;

            #pragma unroll
            for (int ks = 0; ks < 4; ks++) {
                unsigned a[2][4];
                #pragma unroll
                for (int mt = 0; mt < 2; mt++) {
                    int r  = wi * 32 + mt * 16 + (lane & 15);
                    int ch = ks * 2 + (lane >> 4);
                    ldm_x4(xi_base + r * 128 + ((ch ^ (r & 7)) << 4),
                           a[mt][0], a[mt][1], a[mt][2], a[mt][3]);
                }
                #pragma unroll
                for (int h = 0; h < 2; h++) {
                    unsigned br0, br1, br2, br3;
                    int nt2 = wg * 2 + h;
                    int r  = nt2 * 16 + (lane & 15);
                    int ch = ks * 2 + (lane >> 4);
                    ldm_x4(w_base + r * 128 + ((ch ^ (r & 7)) << 4), br0, br1, br2, br3);
                    #pragma unroll
                    for (int mt = 0; mt < 2; mt++) {
                        mma16816(acc[mt][h * 2],     a[mt], br0, br2);
                        mma16816(acc[mt][h * 2 + 1], a[mt], br1, br3);
                    }
                }
            }
        }

        // ---- epilogue for j: dot rows of acc with x_j (this warp's col half) ----
        const char* xjp = cross ? (smem + XJOFF + (size_t)(j & 1) * XTILE)
                                : (smem + (size_t)j * XTILE);
        #pragma unroll
        for (int mt = 0; mt < 2; mt++) {
            const int r0 = wi * 32 + mt * 16 + group;
            const int r1 = r0 + 8;
            float s0 = 0.0f, s1 = 0.0f;
            #pragma unroll
            for (int hn = 0; hn < 4; hn++) {
                const int ntg = wg * 4 + hn;     // global 8-col tile index
                const __half2 x0 = *reinterpret_cast<const __half2*>(
                    xjp + r0 * 128 + ((ntg ^ (r0 & 7)) << 4) + tid4 * 4);
                const __half2 x1 = *reinterpret_cast<const __half2*>(
                    xjp + r1 * 128 + ((ntg ^ (r1 & 7)) << 4) + tid4 * 4);
                float2 f0 = __half22float2(x0);
                float2 f1 = __half22float2(x1);
                s0 = fmaf(acc[mt][hn][0], f0.x, s0);
                s0 = fmaf(acc[mt][hn][1], f0.y, s0);
                s1 = fmaf(acc[mt][hn][2], f1.x, s1);
                s1 = fmaf(acc[mt][hn][3], f1.y, s1);
            }
            tot[mt][0] += s0;
            tot[mt][1] += s1;
        }
    }

    // ---- final reduction + writeback (two wgs add into the same row) ----
    #pragma unroll
    for (int mt = 0; mt < 2; mt++)
        #pragma unroll
        for (int h = 0; h < 2; h++) {
            float v = tot[mt][h];
            v += __shfl_xor_sync(0xffffffffu, v, 1);
            v += __shfl_xor_sync(0xffffffffu, v, 2);
            if (tid4 == 0)
                atomicAdd(out + b0 + wi * 32 + mt * 16 + group + h * 8, v);
        }
}

// ---------------- launch ----------------
extern "C" void kernel_launch(void* const* d_in, const int* in_sizes, int n_in,
                              void* d_out, int out_size) {
    const float* x = (const float*)d_in[0];
    const float* W = (const float*)d_in[1];
    float* out = (float*)d_out;

    static bool attr_done = false;
    if (!attr_done) {
        cudaFuncSetAttribute(fmfm5_kernel, cudaFuncAttributeMaxDynamicSharedMemorySize, DYN_SMEM);
        attr_done = true;
    }

    convert_x_kernel<<<(B * F * 8) / 256, 256>>>(x);
    convert_w_kernel<<<(P * 8 * 64) / 256, 256>>>(W);
    zero_out_kernel<<<B / 256, 256>>>(out);

    dim3 grid(10, NTILE);   // type fast dim -> mixed CTA sizes per wave
    fmfm5_kernel<<<grid, 256, DYN_SMEM>>>(out);
}

// round 7
// speedup vs baseline: 1.1283x; 1.0947x over previous
#include <cuda_runtime.h>
#include <cuda_fp16.h>
#include <cstdint>

// ---------------- problem constants ----------------
constexpr int B  = 16384;
constexpr int F  = 24;
constexpr int P  = 276;
constexpr int MT = 128;                  // b-rows per CTA
constexpr int NTILE = B / MT;            // 128 b-tiles
constexpr int XTILE = MT * 128;          // 16 KB per (tile, field), fp16, swizzled
constexpr int WTILE = 64 * 128;          // 8 KB per pair (W^T fp16, swizzled)
constexpr unsigned XJOFF = 4u * XTILE;            //  65536 (2 xj buffers)
constexpr unsigned WOFF  = XJOFF + 2u * XTILE;    //  98304 (W ring of 2)
constexpr unsigned DYN_SMEM = WOFF + 2u * WTILE;  // 114688 (112 KB -> 2 CTAs/SM)

// ---------------- device scratch (allocation-guard safe) ----------------
__device__ __half g_xs[(size_t)NTILE * F * (XTILE / 2)];  // 48 MB preswizzled x tiles
__device__ __half g_ws[(size_t)P * (WTILE / 2)];          // 2.25 MB preswizzled W^T tiles

// ---------------- helpers ----------------
__device__ __forceinline__ unsigned smem_u32(const void* p) {
    return (unsigned)__cvta_generic_to_shared(p);
}
__device__ __forceinline__ void cp16(unsigned dst, const void* src) {
    asm volatile("cp.async.cg.shared.global [%0], [%1], 16;" :: "r"(dst), "l"(src));
}
__device__ __forceinline__ void cp_commit() {
    asm volatile("cp.async.commit_group;" ::: "memory");
}
__device__ __forceinline__ void cp_wait0() {
    asm volatile("cp.async.wait_group 0;" ::: "memory");
}
__device__ __forceinline__ void ldm_x4(unsigned addr, unsigned& r0, unsigned& r1,
                                       unsigned& r2, unsigned& r3) {
    asm volatile("ldmatrix.sync.aligned.m8n8.x4.shared.b16 {%0,%1,%2,%3}, [%4];"
                 : "=r"(r0), "=r"(r1), "=r"(r2), "=r"(r3)
                 : "r"(addr));
}
__device__ __forceinline__ void mma16816(float* c, const unsigned* a,
                                         unsigned b0, unsigned b1) {
    asm volatile(
        "mma.sync.aligned.m16n8k16.row.col.f32.f16.f16.f32 "
        "{%0,%1,%2,%3}, {%4,%5,%6,%7}, {%8,%9}, {%0,%1,%2,%3};"
        : "+f"(c[0]), "+f"(c[1]), "+f"(c[2]), "+f"(c[3])
        : "r"(a[0]), "r"(a[1]), "r"(a[2]), "r"(a[3]), "r"(b0), "r"(b1));
}
__device__ __forceinline__ int pidx(int fi, int fj) {   // triu row-major pair index
    return fi * (2 * F - fi - 1) / 2 + (fj - fi - 1);
}

// ---------------- prepass: convert + pre-swizzle ----------------
__global__ void convert_x_kernel(const float* __restrict__ x) {
    int t = blockIdx.x * blockDim.x + threadIdx.x;      // chunk id < B*F*8
    int c = t & 7;
    int bf = t >> 3;
    int f = bf % F;
    int b = bf / F;
    const float4* src = reinterpret_cast<const float4*>(x + ((size_t)bf * 64 + c * 8));
    float4 v0 = src[0], v1 = src[1];
    union { uint4 u; __half2 h[4]; } pk;
    pk.h[0] = __floats2half2_rn(v0.x, v0.y);
    pk.h[1] = __floats2half2_rn(v0.z, v0.w);
    pk.h[2] = __floats2half2_rn(v1.x, v1.y);
    pk.h[3] = __floats2half2_rn(v1.z, v1.w);
    int tile = b >> 7, r = b & 127;
    size_t off = ((size_t)(tile * 24 + f) << 14) + r * 128 + ((c ^ (r & 7)) << 4);
    *reinterpret_cast<uint4*>(reinterpret_cast<char*>(g_xs) + off) = pk.u;
}
// W[p,d,e] fp32 -> preswizzled W^T tile: row e, chunk c holds d = c*8..c*8+7
__global__ void convert_w_kernel(const float* __restrict__ W) {
    int t = blockIdx.x * blockDim.x + threadIdx.x;      // < P*8*64
    int e = t & 63;
    int pc = t >> 6;
    int c = pc & 7;
    int p = pc >> 3;
    const float* base = W + (size_t)p * 4096 + (size_t)c * 8 * 64 + e;
    union { uint4 u; __half h[8]; } pk;
    #pragma unroll
    for (int k = 0; k < 8; k++) pk.h[k] = __float2half_rn(base[k * 64]);
    size_t off = (size_t)p * 8192 + e * 128 + ((c ^ (e & 7)) << 4);
    *reinterpret_cast<uint4*>(reinterpret_cast<char*>(g_ws) + off) = pk.u;
}
__global__ void zero_out_kernel(float* __restrict__ out) {
    out[blockIdx.x * blockDim.x + threadIdx.x] = 0.0f;
}

// ---------------- main kernel ----------------
// 24 fields in 6 groups of 4. grid = (21 types, 128 b-tiles), 256 thr, 2 CTAs/SM.
//   type 0..5  : within-group g      -> 6 pairs  (j=1..3, i<j)
//   type 6..20 : cross block (gi,gj) -> 16 pairs (j=0..3, i=0..3)
// 4 xi tiles resident (64 KB); xj double-buffered (32 KB); W ring-2 (16 KB).
// Per pair: one cp.async group + one barrier; K-concat per j; epilogue at j end.
__global__ __launch_bounds__(256, 2) void fmfm6_kernel(float* __restrict__ out) {
    extern __shared__ __align__(1024) char smem[];
    const int tid  = threadIdx.x;
    const int warp = tid >> 5, lane = tid & 31;
    const int wi = warp & 3, wg = warp >> 2;
    const int group = lane >> 2, tid4 = lane & 3;
    const int type = blockIdx.x;
    const int tile = blockIdx.y;
    const int b0   = tile * MT;

    const bool cross = (type >= 6);
    int fi0, fj0, npairs;
    if (!cross) { fi0 = type * 4; fj0 = fi0; npairs = 6; }
    else {
        const int c = type - 6;
        const int ga[15] = {0,0,0,0,0,1,1,1,1,2,2,2,3,3,4};
        const int gb[15] = {1,2,3,4,5,2,3,4,5,3,4,5,4,5,5};
        fi0 = ga[c] * 4; fj0 = gb[c] * 4; npairs = 16;
    }
    // within-type pair decode tables (j-major)
    const int wj[6] = {1,2,2,3,3,3};
    const int wiid[6] = {0,0,1,0,1,2};

    const unsigned sb = smem_u32(smem);
    const char* xs = reinterpret_cast<const char*>(g_xs);
    const char* ws = reinterpret_cast<const char*>(g_ws);

    // ---- preload: 4 xi tiles + W(pair 0) + xj(j=0) for cross ----
    #pragma unroll
    for (int s = 0; s < 4; s++) {
        const char* g = xs + ((size_t)(tile * 24 + fi0 + s) << 14);
        #pragma unroll
        for (int c = tid; c < 1024; c += 256)
            cp16(sb + s * XTILE + c * 16, g + c * 16);
    }
    {
        int p0 = cross ? pidx(fi0, fj0) : pidx(fi0, fi0 + 1);
        const char* g = ws + (size_t)p0 * WTILE;
        #pragma unroll
        for (int c = tid; c < 512; c += 256)
            cp16(sb + WOFF + c * 16, g + c * 16);
        if (cross) {
            const char* gx = xs + ((size_t)(tile * 24 + fj0) << 14);
            #pragma unroll
            for (int c = tid; c < 1024; c += 256)
                cp16(sb + XJOFF + c * 16, gx + c * 16);
        }
    }
    cp_commit();

    float tot[2][2] = {{0.f, 0.f}, {0.f, 0.f}};
    float acc[2][4][4];

    for (int n = 0; n < npairs; n++) {
        const int j = cross ? (n >> 2) : wj[n];
        const int i = cross ? (n & 3)  : wiid[n];
        const bool jlast = cross ? (i == 3) : (i == j - 1);

        cp_wait0();
        __syncthreads();                 // W slot n&1 (+ xj/xi on n=0) published

        // ---- prefetch pair n+1 (W; + xj if it starts a new j on cross) ----
        {
            int m = n + 1;
            if (m < npairs) {
                int j2 = cross ? (m >> 2) : wj[m];
                int i2 = cross ? (m & 3)  : wiid[m];
                int a  = fi0 + i2;
                int bq = cross ? fj0 + j2 : fi0 + j2;
                const char* g = ws + (size_t)pidx(a, bq) * WTILE;
                unsigned wdst = sb + WOFF + ((unsigned)(m & 1)) * WTILE;
                #pragma unroll
                for (int c = tid; c < 512; c += 256)
                    cp16(wdst + c * 16, g + c * 16);
                if (cross && i2 == 0) {
                    const char* gx = xs + ((size_t)(tile * 24 + fj0 + j2) << 14);
                    unsigned xdst = sb + XJOFF + ((unsigned)(j2 & 1)) * XTILE;
                    #pragma unroll
                    for (int c = tid; c < 1024; c += 256)
                        cp16(xdst + c * 16, gx + c * 16);
                }
            }
            cp_commit();                 // empty group on tail keeps accounting uniform
        }

        if (i == 0) {
            #pragma unroll
            for (int a = 0; a < 2; a++)
                #pragma unroll
                for (int b = 0; b < 4; b++)
                    #pragma unroll
                    for (int c = 0; c < 4; c++) acc[a][b][c] = 0.0f;
        }

        // ---- MMA for pair n (K-concat into acc) ----
        const unsigned xi_base = sb + (unsigned)i * XTILE;
        const unsigned w_base  = sb + WOFF + ((unsigned)(n & 1)) * WTILE;

        #pragma unroll
        for (int ks = 0; ks < 4; ks++) {
            unsigned a[2][4];
            #pragma unroll
            for (int mt = 0; mt < 2; mt++) {
                int r  = wi * 32 + mt * 16 + (lane & 15);
                int ch = ks * 2 + (lane >> 4);
                ldm_x4(xi_base + r * 128 + ((ch ^ (r & 7)) << 4),
                       a[mt][0], a[mt][1], a[mt][2], a[mt][3]);
            }
            #pragma unroll
            for (int h = 0; h < 2; h++) {
                unsigned br0, br1, br2, br3;
                int nt2 = wg * 2 + h;
                int r  = nt2 * 16 + (lane & 15);
                int ch = ks * 2 + (lane >> 4);
                ldm_x4(w_base + r * 128 + ((ch ^ (r & 7)) << 4), br0, br1, br2, br3);
                #pragma unroll
                for (int mt = 0; mt < 2; mt++) {
                    mma16816(acc[mt][h * 2],     a[mt], br0, br2);
                    mma16816(acc[mt][h * 2 + 1], a[mt], br1, br3);
                }
            }
        }

        // ---- epilogue at end of j: dot rows of acc with x_j ----
        if (jlast) {
            const char* xjp = cross ? (smem + XJOFF + (size_t)(j & 1) * XTILE)
                                    : (smem + (size_t)j * XTILE);
            #pragma unroll
            for (int mt = 0; mt < 2; mt++) {
                const int r0 = wi * 32 + mt * 16 + group;
                const int r1 = r0 + 8;
                float s0 = 0.0f, s1 = 0.0f;
                #pragma unroll
                for (int hn = 0; hn < 4; hn++) {
                    const int ntg = wg * 4 + hn;     // global 8-col tile index
                    const __half2 x0 = *reinterpret_cast<const __half2*>(
                        xjp + r0 * 128 + ((ntg ^ (r0 & 7)) << 4) + tid4 * 4);
                    const __half2 x1 = *reinterpret_cast<const __half2*>(
                        xjp + r1 * 128 + ((ntg ^ (r1 & 7)) << 4) + tid4 * 4);
                    float2 f0 = __half22float2(x0);
                    float2 f1 = __half22float2(x1);
                    s0 = fmaf(acc[mt][hn][0], f0.x, s0);
                    s0 = fmaf(acc[mt][hn][1], f0.y, s0);
                    s1 = fmaf(acc[mt][hn][2], f1.x, s1);
                    s1 = fmaf(acc[mt][hn][3], f1.y, s1);
                }
                tot[mt][0] += s0;
                tot[mt][1] += s1;
            }
        }
    }

    // ---- final reduction + writeback ----
    #pragma unroll
    for (int mt = 0; mt < 2; mt++)
        #pragma unroll
        for (int h = 0; h < 2; h++) {
            float v = tot[mt][h];
            v += __shfl_xor_sync(0xffffffffu, v, 1);
            v += __shfl_xor_sync(0xffffffffu, v, 2);
            if (tid4 == 0)
                atomicAdd(out + b0 + wi * 32 + mt * 16 + group + h * 8, v);
        }
}

// ---------------- launch ----------------
extern "C" void kernel_launch(void* const* d_in, const int* in_sizes, int n_in,
                              void* d_out, int out_size) {
    const float* x = (const float*)d_in[0];
    const float* W = (const float*)d_in[1];
    float* out = (float*)d_out;

    static bool attr_done = false;
    if (!attr_done) {
        cudaFuncSetAttribute(fmfm6_kernel, cudaFuncAttributeMaxDynamicSharedMemorySize, DYN_SMEM);
        attr_done = true;
    }

    convert_x_kernel<<<(B * F * 8) / 256, 256>>>(x);
    convert_w_kernel<<<(P * 8 * 64) / 256, 256>>>(W);
    zero_out_kernel<<<B / 256, 256>>>(out);

    dim3 grid(21, NTILE);   // type fast dim -> mixed CTA lengths per wave
    fmfm6_kernel<<<grid, 256, DYN_SMEM>>>(out);
}